// round 9
// baseline (speedup 1.0000x reference)
#include <cuda_runtime.h>
#include <cstdint>

// ---------------------------------------------------------------------------
// Problem constants
//   x      [32, 256, 32, 32] f32
//   weight [256, 256, 3, 3]  f32
//   gamma  [1024] f32, beta [1024] f32
//   out    [32, 256, 32, 32] f32
//
// Strategy: binary-weight conv as tf32 mma.sync GEMM (base PTX), 2-pass
// hi/lo tf32 split of x, B = +-1 (tf32-exact), alpha folded into BN scale.
// Near-threshold sign decisions (|margin| < sc*TAU) are flagged in k_out
// and recomputed EXACTLY (double accumulation from raw x/weight) in k_fix,
// so only reference-side fp32 noise can cause output flips.
// ---------------------------------------------------------------------------

#define TAU   0.01f          // recheck band in S-units (sigma_S ~ 24)
#define CAP   1048576        // flagged-pixel list capacity

static __device__ float g_wB[4 * 9 * 2 * 32 * 256];   // [g][tap][cc][k][co] = +-1.0f
static __device__ float g_alpha[256];
static __device__ float g_psum[33554432];             // [b][g*256+co][h][w]  (holds S)
static __device__ float g_scale[1024];
static __device__ float g_bias[1024];
static __device__ int   g_cnt;
static __device__ int   g_list[CAP];

// ---------------------------------------------------------------------------
// K0: alpha[co] = mean |w|, +-1 weight pack, and zero the flag counter.
// ---------------------------------------------------------------------------
__global__ void k_prep(const float* __restrict__ w) {
    const int co = blockIdx.x;
    const int t  = threadIdx.x;          // 256 threads
    if (co == 0 && t == 0) g_cnt = 0;
    __shared__ float red[256];
    const float* wc = w + co * 2304;
    float s = 0.0f;
    for (int i = t; i < 2304; i += 256) s += fabsf(wc[i]);
    red[t] = s;
    __syncthreads();
    for (int off = 128; off; off >>= 1) {
        if (t < off) red[t] += red[t + off];
        __syncthreads();
    }
    if (t == 0) g_alpha[co] = red[0] * (1.0f / 2304.0f);
    for (int i = t; i < 2304; i += 256) {
        const int ci  = i / 9;
        const int tap = i - ci * 9;
        const int g   = ci >> 6;
        const int cig = ci & 63;
        const int cc  = cig >> 5;
        const int k   = cig & 31;
        const float v = wc[i];
        g_wB[((((g * 9 + tap) * 2 + cc) * 32) + k) * 256 + co] = (v >= 0.0f) ? 1.0f : -1.0f;
    }
}

// ---------------------------------------------------------------------------
// K1: tf32 mma.sync conv. CTA = D[128 px][256 co] for (b, g, rowTile).
// 512 threads = 16 warps (4 M x 4 N); warp tile 32 px x 64 co.
// smem floats: B[0,8448) XHI[8448,22272) XLO[22272,36096)
// ---------------------------------------------------------------------------
#define SM_B    0
#define SM_XHI  8448
#define SM_XLO  22272
#define SM_FLOATS 36096
#define SM_BYTES (SM_FLOATS * 4)

__device__ __forceinline__ void mma_tf32(float& d0, float& d1, float& d2, float& d3,
                                         float a0, float a1, float a2, float a3,
                                         float b0, float b1) {
    asm volatile(
        "mma.sync.aligned.m16n8k8.row.col.f32.tf32.tf32.f32 "
        "{%0,%1,%2,%3}, {%4,%5,%6,%7}, {%8,%9}, {%0,%1,%2,%3};"
        : "+f"(d0), "+f"(d1), "+f"(d2), "+f"(d3)
        : "r"(__float_as_uint(a0)), "r"(__float_as_uint(a1)),
          "r"(__float_as_uint(a2)), "r"(__float_as_uint(a3)),
          "r"(__float_as_uint(b0)), "r"(__float_as_uint(b1)));
}

__device__ __forceinline__ float tf32_rna(float v) {
    uint32_t b; asm("cvt.rna.tf32.f32 %0, %1;" : "=r"(b) : "f"(v));
    return __uint_as_float(b);
}

__global__ void __launch_bounds__(512, 1)
k_conv(const float* __restrict__ x) {
    extern __shared__ float sm[];
    const int tid = threadIdx.x;
    const int wid = tid >> 5;
    const int lane = tid & 31;
    const int lq  = lane >> 2;     // 0..7
    const int lr4 = lane & 3;      // 0..3
    const int warpM = wid >> 2;    // 0..3 -> image row within tile
    const int warpN = wid & 3;     // 0..3 -> 64-co slice

    const int b  = blockIdx.z;
    const int g  = blockIdx.y;
    const int pt = blockIdx.x;     // 0..7
    const int r0 = pt * 4;

    // ---- stage x slab, hi/lo tf32 split: [64 ci][6 rows][36 cols] ----
    const float* xg = x + (size_t)(b * 256 + g * 64) * 1024;
    for (int i = tid; i < 13824; i += 512) {
        const int ci  = i / 216;
        const int rem = i - ci * 216;
        const int lrr = rem / 36;
        const int lc  = rem - lrr * 36;
        const int gr  = r0 - 1 + lrr;
        const int gc  = lc - 1;
        float v = 0.0f;
        if ((unsigned)gr < 32u && (unsigned)gc < 32u)
            v = xg[ci * 1024 + gr * 32 + gc];
        const float hi = tf32_rna(v);
        sm[SM_XHI + i] = hi;
        sm[SM_XLO + i] = tf32_rna(v - hi);
    }

    float acc[2][8][4];
#pragma unroll
    for (int mt = 0; mt < 2; mt++)
#pragma unroll
        for (int n = 0; n < 8; n++)
#pragma unroll
            for (int k = 0; k < 4; k++) acc[mt][n][k] = 0.0f;

    const float* srcB = g_wB + (size_t)g * 9 * 2 * 8192;

    for (int step = 0; step < 18; ++step) {
        __syncthreads();   // previous step's B reads done / slab ready (step 0)
        // ---- stage B chunk [32 k][256 co] into padded [32][264] ----
        const float* src = srcB + (size_t)step * 8192;
        for (int i = tid; i < 8192; i += 512) {
            sm[SM_B + (i >> 8) * 264 + (i & 255)] = src[i];
        }
        __syncthreads();

        const int tap = step >> 1;
        const int cc  = step & 1;
        const int kh  = tap / 3;
        const int kw  = tap - kh * 3;
        const int abase = (cc * 32 + lr4) * 216 + (warpM + kh) * 36 + kw + lq;
        const float* bpBase = sm + SM_B + lr4 * 264 + warpN * 64 + lq;

#pragma unroll
        for (int ks = 0; ks < 4; ++ks) {
            float b0[8], b1[8];
            const float* bp = bpBase + ks * 8 * 264;
#pragma unroll
            for (int n = 0; n < 8; ++n) {
                b0[n] = bp[n * 8];
                b1[n] = bp[4 * 264 + n * 8];
            }
#pragma unroll
            for (int pass = 0; pass < 2; ++pass) {
                const float* sx = sm + (pass ? SM_XLO : SM_XHI) + abase + ks * 8 * 216;
                float a[2][4];
#pragma unroll
                for (int mt = 0; mt < 2; ++mt) {
                    const float* p = sx + mt * 16;
                    a[mt][0] = p[0];
                    a[mt][1] = p[8];
                    a[mt][2] = p[4 * 216];
                    a[mt][3] = p[4 * 216 + 8];
                }
#pragma unroll
                for (int n = 0; n < 8; ++n) {
#pragma unroll
                    for (int mt = 0; mt < 2; ++mt) {
                        mma_tf32(acc[mt][n][0], acc[mt][n][1], acc[mt][n][2], acc[mt][n][3],
                                 a[mt][0], a[mt][1], a[mt][2], a[mt][3],
                                 b0[n], b1[n]);
                    }
                }
            }
        }
    }

    // ---- epilogue: D[px][co] -> g_psum[b][g*256+co][px] ----
    const int rimg = r0 + warpM;
#pragma unroll
    for (int mt = 0; mt < 2; ++mt) {
        const int px0 = rimg * 32 + mt * 16 + lq;
#pragma unroll
        for (int n = 0; n < 8; ++n) {
            const int co = g * 256 + warpN * 64 + n * 8 + lr4 * 2;
            float* base = g_psum + ((size_t)(b * 1024 + co)) * 1024;
            base[px0]            = acc[mt][n][0];
            base[1024 + px0]     = acc[mt][n][1];
            base[px0 + 8]        = acc[mt][n][2];
            base[1024 + px0 + 8] = acc[mt][n][3];
        }
    }
}

// ---------------------------------------------------------------------------
// K2: per-channel stats over S in g_psum -> scale/bias (alpha + eps folded).
// ---------------------------------------------------------------------------
__global__ void k_stats(const float* __restrict__ gamma,
                        const float* __restrict__ beta) {
    const int ch = blockIdx.x;     // 1024
    const int t  = threadIdx.x;    // 256
    __shared__ float rs[256], rq[256];
    float s = 0.0f, q = 0.0f;
    for (int i = t; i < 32768; i += 256) {
        const int bb = i >> 10;
        const int px = i & 1023;
        const float v = g_psum[((size_t)(bb * 1024 + ch)) * 1024 + px];
        s += v; q += v * v;
    }
    rs[t] = s; rq[t] = q;
    __syncthreads();
    for (int off = 128; off; off >>= 1) {
        if (t < off) { rs[t] += rs[t + off]; rq[t] += rq[t + off]; }
        __syncthreads();
    }
    if (t == 0) {
        const float mean = rs[0] * (1.0f / 32768.0f);
        const float var  = rq[0] * (1.0f / 32768.0f) - mean * mean;
        const float a    = g_alpha[ch & 255];
        const float inv  = gamma[ch] / sqrtf(a * a * var + 1e-5f);
        const float sc   = a * inv;                 // scale applied to S
        g_scale[ch] = sc;
        g_bias[ch]  = beta[ch] - mean * sc;
    }
}

// ---------------------------------------------------------------------------
// K3: threshold + merge + qrelu LUT; flag near-threshold pixels for k_fix.
// ---------------------------------------------------------------------------
__global__ void k_out(float* __restrict__ out) {
    const int idx = blockIdx.x * 256 + threadIdx.x;   // quad index
    const int b    = idx >> 16;
    const int qb   = idx & 65535;
    const int co   = qb >> 8;
    const int pix4 = qb & 255;

    const float4* pb = reinterpret_cast<const float4*>(g_psum);
    int c0 = 0, c1 = 0, c2 = 0, c3 = 0;
    bool f0 = false, f1 = false, f2 = false, f3 = false;
#pragma unroll
    for (int g = 0; g < 4; g++) {
        const int chan = g * 256 + co;
        const float4 p = pb[(size_t)(b * 1024 + chan) * 256 + pix4];
        const float sc = g_scale[chan];
        const float bi = g_bias[chan];
        const float band = fabsf(sc) * TAU;
        const float m0 = p.x * sc + bi;
        const float m1 = p.y * sc + bi;
        const float m2 = p.z * sc + bi;
        const float m3 = p.w * sc + bi;
        c0 += (m0 >= 0.0f); f0 |= (fabsf(m0) < band);
        c1 += (m1 >= 0.0f); f1 |= (fabsf(m1) < band);
        c2 += (m2 >= 0.0f); f2 |= (fabsf(m2) < band);
        c3 += (m3 >= 0.0f); f3 |= (fabsf(m3) < band);
    }
    const float Q3 = (8.0f / 15.0f) * 4.0f;
    float4 o;
    o.x = (c0 == 4) ? 4.0f : ((c0 == 3) ? Q3 : 0.0f);
    o.y = (c1 == 4) ? 4.0f : ((c1 == 3) ? Q3 : 0.0f);
    o.z = (c2 == 4) ? 4.0f : ((c2 == 3) ? Q3 : 0.0f);
    o.w = (c3 == 4) ? 4.0f : ((c3 == 3) ? Q3 : 0.0f);
    reinterpret_cast<float4*>(out)[idx] = o;

    if (f0 | f1 | f2 | f3) {
        const int base = (b << 18) | (co << 10) | (pix4 << 2);
#pragma unroll
        for (int comp = 0; comp < 4; ++comp) {
            const bool f = (comp == 0) ? f0 : (comp == 1) ? f1 : (comp == 2) ? f2 : f3;
            if (f) {
                const int slot = atomicAdd(&g_cnt, 1);
                if (slot < CAP) g_list[slot] = base | comp;
            }
        }
    }
}

// ---------------------------------------------------------------------------
// K4: exact (double) recompute of flagged pixels' decisions; rewrite out.
// Idempotent: result independent of list order / duplicates.
// ---------------------------------------------------------------------------
__global__ void k_fix(const float* __restrict__ x, const float* __restrict__ w,
                      float* __restrict__ out) {
    const int n = (g_cnt < CAP) ? g_cnt : CAP;
    for (int i = blockIdx.x * blockDim.x + threadIdx.x; i < n;
         i += gridDim.x * blockDim.x) {
        const int item = g_list[i];
        const int b   = item >> 18;
        const int co  = (item >> 10) & 255;
        const int pix = item & 1023;
        const int h = pix >> 5, wp = pix & 31;
        int c = 0;
#pragma unroll 1
        for (int g = 0; g < 4; g++) {
            const int chan = g * 256 + co;
            const float sc = g_scale[chan];
            const float bi = g_bias[chan];
            const float S  = g_psum[((size_t)(b * 1024 + chan)) * 1024 + pix];
            const float m  = S * sc + bi;
            int bit;
            if (fabsf(m) < fabsf(sc) * TAU) {
                double s = 0.0;
                const float* xb = x + ((size_t)(b * 256 + g * 64)) * 1024;
                const float* wb = w + (size_t)co * 2304 + (size_t)g * 64 * 9;
                for (int cig = 0; cig < 64; cig++) {
                    const float* xc = xb + cig * 1024;
                    const float* wc = wb + cig * 9;
#pragma unroll
                    for (int kh = 0; kh < 3; kh++) {
                        const int hh = h + kh - 1;
                        if ((unsigned)hh >= 32u) continue;
#pragma unroll
                        for (int kw = 0; kw < 3; kw++) {
                            const int ww = wp + kw - 1;
                            if ((unsigned)ww >= 32u) continue;
                            const float xv = __ldg(xc + hh * 32 + ww);
                            s += (__ldg(wc + kh * 3 + kw) >= 0.0f) ? (double)xv
                                                                   : -(double)xv;
                        }
                    }
                }
                const double md = s * (double)sc + (double)bi;
                bit = (md >= 0.0);
            } else {
                bit = (m >= 0.0f);
            }
            c += bit;
        }
        const float Q3 = (8.0f / 15.0f) * 4.0f;
        out[((size_t)(b * 256 + co)) * 1024 + pix] =
            (c == 4) ? 4.0f : ((c == 3) ? Q3 : 0.0f);
    }
}

// ---------------------------------------------------------------------------
extern "C" void kernel_launch(void* const* d_in, const int* in_sizes, int n_in,
                              void* d_out, int out_size) {
    const float* x      = (const float*)d_in[0];
    const float* weight = (const float*)d_in[1];
    const float* gamma  = (const float*)d_in[2];
    const float* beta   = (const float*)d_in[3];
    float* out = (float*)d_out;

    cudaFuncSetAttribute(k_conv, cudaFuncAttributeMaxDynamicSharedMemorySize, SM_BYTES);

    k_prep<<<256, 256>>>(weight);
    k_conv<<<dim3(8, 4, 32), 512, SM_BYTES>>>(x);
    k_stats<<<1024, 256>>>(gamma, beta);
    k_out<<<8192, 256>>>(out);
    k_fix<<<512, 128>>>(x, weight, out);
}

// round 12
// speedup vs baseline: 1.1990x; 1.1990x over previous
#include <cuda_runtime.h>
#include <cuda_bf16.h>
#include <cstdint>

// ---------------------------------------------------------------------------
// Problem constants
//   x      [32, 256, 32, 32] f32
//   weight [256, 256, 3, 3]  f32
//   gamma  [1024] f32, beta [1024] f32
//   out    [32, 256, 32, 32] f32
//
// Strategy: binary-weight conv as bf16 m16n8k16 mma.sync GEMM (base PTX).
//   psum = alpha * S,  S = sum of (+-1)*x
//   B = +-1 (bf16-exact); A = x split hi/lo bf16 (residual <= 2^-18|x|),
//   both passes accumulated into the same fp32 C fragments.
//   alpha folded into the BN scale in k_stats.
//   Near-threshold sign decisions (|margin| < sc*TAU) are flagged in k_out
//   and recomputed EXACTLY (double accumulation from raw x/weight) in k_fix.
// ---------------------------------------------------------------------------

#define TAU   0.01f          // recheck band in S-units (sigma_S ~ 24)
#define CAP   1048576        // flagged-pixel list capacity

static __device__ uint32_t g_wB[4 * 9 * 32 * 256];    // [g][tap][kpair][co] bf16x2 (+-1)
static __device__ float    g_alpha[256];
static __device__ float    g_psum[33554432];          // [b][g*256+co][h][w]  (holds S)
static __device__ float    g_scale[1024];
static __device__ float    g_bias[1024];
static __device__ int      g_cnt;
static __device__ int      g_list[CAP];

// ---------------------------------------------------------------------------
// K0: alpha[co] = mean |w|, bf16 +-1 weight pack, zero the flag counter.
// g_wB halves written as 16-bit stores (no races: distinct addresses).
// ---------------------------------------------------------------------------
__global__ void k_prep(const float* __restrict__ w) {
    const int co = blockIdx.x;
    const int t  = threadIdx.x;          // 256 threads
    if (co == 0 && t == 0) g_cnt = 0;
    __shared__ float red[256];
    const float* wc = w + co * 2304;
    float s = 0.0f;
    for (int i = t; i < 2304; i += 256) s += fabsf(wc[i]);
    red[t] = s;
    __syncthreads();
    for (int off = 128; off; off >>= 1) {
        if (t < off) red[t] += red[t + off];
        __syncthreads();
    }
    if (t == 0) g_alpha[co] = red[0] * (1.0f / 2304.0f);
    uint16_t* wb16 = reinterpret_cast<uint16_t*>(g_wB);
    for (int i = t; i < 2304; i += 256) {
        const int ci  = i / 9;
        const int tap = i - ci * 9;
        const int g   = ci >> 6;
        const int cig = ci & 63;
        const int kp  = cig >> 1;
        const int hlf = cig & 1;
        const float v = wc[i];
        // bf16(+1)=0x3F80, bf16(-1)=0xBF80
        wb16[((((size_t)(g * 9 + tap) * 32 + kp) * 256) + co) * 2 + hlf] =
            (v >= 0.0f) ? 0x3F80u : 0xBF80u;
    }
}

// ---------------------------------------------------------------------------
// K1: bf16 m16n8k16 mma.sync conv. CTA = D[128 px][256 co] for (b,g,rowTile).
// 512 threads = 16 warps (4 M x 4 N); warp tile 32 px x 64 co.
// smem uint32 words: B[0,8448) XHI[8448,15360) XLO[15360,22272)
//   B:   [32 kpair][264 pad] bf16x2 (k even/odd)
//   Xs:  [32 cipair][6 rows][36 cols] bf16x2 (ci even/odd)
// ---------------------------------------------------------------------------
#define SM_B    0
#define SM_XHI  8448
#define SM_XLO  15360
#define SM_WORDS 22272
#define SM_BYTES (SM_WORDS * 4)

__device__ __forceinline__ void mma_bf16(float& d0, float& d1, float& d2, float& d3,
                                         uint32_t a0, uint32_t a1, uint32_t a2, uint32_t a3,
                                         uint32_t b0, uint32_t b1) {
    asm volatile(
        "mma.sync.aligned.m16n8k16.row.col.f32.bf16.bf16.f32 "
        "{%0,%1,%2,%3}, {%4,%5,%6,%7}, {%8,%9}, {%0,%1,%2,%3};"
        : "+f"(d0), "+f"(d1), "+f"(d2), "+f"(d3)
        : "r"(a0), "r"(a1), "r"(a2), "r"(a3), "r"(b0), "r"(b1));
}

__device__ __forceinline__ uint32_t bf16_split_pack(float v0, float v1, float& r0, float& r1) {
    const __nv_bfloat16 h0 = __float2bfloat16_rn(v0);
    const __nv_bfloat16 h1 = __float2bfloat16_rn(v1);
    r0 = v0 - __bfloat162float(h0);
    r1 = v1 - __bfloat162float(h1);
    return (uint32_t)__bfloat16_as_ushort(h0) | ((uint32_t)__bfloat16_as_ushort(h1) << 16);
}
__device__ __forceinline__ uint32_t bf16_pack(float v0, float v1) {
    return (uint32_t)__bfloat16_as_ushort(__float2bfloat16_rn(v0)) |
           ((uint32_t)__bfloat16_as_ushort(__float2bfloat16_rn(v1)) << 16);
}

__global__ void __launch_bounds__(512, 1)
k_conv(const float* __restrict__ x) {
    extern __shared__ uint32_t smu[];
    const int tid  = threadIdx.x;
    const int wid  = tid >> 5;
    const int lane = tid & 31;
    const int lq   = lane >> 2;     // 0..7
    const int lr4  = lane & 3;      // 0..3
    const int warpM = wid >> 2;     // 0..3 -> image row within tile
    const int warpN = wid & 3;      // 0..3 -> 64-co slice

    const int b  = blockIdx.z;
    const int g  = blockIdx.y;
    const int pt = blockIdx.x;      // 0..7
    const int r0 = pt * 4;

    // ---- stage x slab, hi/lo bf16 split, ci pairs packed ----
    const float* xg = x + (size_t)(b * 256 + g * 64) * 1024;
    for (int i = tid; i < 6912; i += 512) {
        const int cp  = i / 216;           // ci pair (ci = 2cp, 2cp+1)
        const int rem = i - cp * 216;
        const int lrr = rem / 36;
        const int lc  = rem - lrr * 36;
        const int gr  = r0 - 1 + lrr;
        const int gc  = lc - 1;
        float v0 = 0.0f, v1 = 0.0f;
        if ((unsigned)gr < 32u && (unsigned)gc < 32u) {
            v0 = xg[(2 * cp) * 1024 + gr * 32 + gc];
            v1 = xg[(2 * cp + 1) * 1024 + gr * 32 + gc];
        }
        float r0f, r1f;
        smu[SM_XHI + i] = bf16_split_pack(v0, v1, r0f, r1f);
        smu[SM_XLO + i] = bf16_pack(r0f, r1f);
    }

    float acc[2][8][4];
#pragma unroll
    for (int mt = 0; mt < 2; mt++)
#pragma unroll
        for (int n = 0; n < 8; n++)
#pragma unroll
            for (int k = 0; k < 4; k++) acc[mt][n][k] = 0.0f;

    const uint32_t* srcB = g_wB + (size_t)g * 9 * 8192;

    for (int tap = 0; tap < 9; ++tap) {
        __syncthreads();   // previous tap's B reads done / slab ready (tap 0)
        // ---- stage B chunk [32 kpair][256 co] into padded [32][264] ----
        const uint32_t* src = srcB + (size_t)tap * 8192;
        for (int i = tid; i < 8192; i += 512) {
            smu[SM_B + (i >> 8) * 264 + (i & 255)] = src[i];
        }
        __syncthreads();

        const int kh = tap / 3;
        const int kw = tap - kh * 3;
        const int abase = (warpM + kh) * 36 + kw + lq;
        const uint32_t* bp0 = smu + SM_B + lr4 * 264 + warpN * 64 + lq;

#pragma unroll
        for (int kc = 0; kc < 4; ++kc) {     // K16 chunk over ci (8 kpairs each)
            uint32_t b0[8], b1[8];
            const uint32_t* bp = bp0 + kc * 8 * 264;
#pragma unroll
            for (int n = 0; n < 8; ++n) {
                b0[n] = bp[n * 8];
                b1[n] = bp[4 * 264 + n * 8];
            }
#pragma unroll
            for (int pass = 0; pass < 2; ++pass) {
                const uint32_t* sxp = smu + (pass ? SM_XLO : SM_XHI)
                                      + (kc * 8 + lr4) * 216 + abase;
                uint32_t A[2][4];
#pragma unroll
                for (int mt = 0; mt < 2; ++mt) {
                    A[mt][0] = sxp[mt * 16];
                    A[mt][1] = sxp[mt * 16 + 8];
                    A[mt][2] = sxp[4 * 216 + mt * 16];
                    A[mt][3] = sxp[4 * 216 + mt * 16 + 8];
                }
#pragma unroll
                for (int n = 0; n < 8; ++n) {
#pragma unroll
                    for (int mt = 0; mt < 2; ++mt) {
                        mma_bf16(acc[mt][n][0], acc[mt][n][1], acc[mt][n][2], acc[mt][n][3],
                                 A[mt][0], A[mt][1], A[mt][2], A[mt][3],
                                 b0[n], b1[n]);
                    }
                }
            }
        }
    }

    // ---- epilogue: D[px][co] -> g_psum[b][g*256+co][px] ----
    const int rimg = r0 + warpM;
#pragma unroll
    for (int mt = 0; mt < 2; ++mt) {
        const int px0 = rimg * 32 + mt * 16 + lq;
#pragma unroll
        for (int n = 0; n < 8; ++n) {
            const int co = g * 256 + warpN * 64 + n * 8 + lr4 * 2;
            float* base = g_psum + ((size_t)(b * 1024 + co)) * 1024;
            base[px0]            = acc[mt][n][0];
            base[1024 + px0]     = acc[mt][n][1];
            base[px0 + 8]        = acc[mt][n][2];
            base[1024 + px0 + 8] = acc[mt][n][3];
        }
    }
}

// ---------------------------------------------------------------------------
// K2: per-channel stats over S in g_psum -> scale/bias (alpha + eps folded).
// ---------------------------------------------------------------------------
__global__ void k_stats(const float* __restrict__ gamma,
                        const float* __restrict__ beta) {
    const int ch = blockIdx.x;     // 1024
    const int t  = threadIdx.x;    // 256
    __shared__ float rs[256], rq[256];
    float s = 0.0f, q = 0.0f;
    for (int i = t; i < 32768; i += 256) {
        const int bb = i >> 10;
        const int px = i & 1023;
        const float v = g_psum[((size_t)(bb * 1024 + ch)) * 1024 + px];
        s += v; q += v * v;
    }
    rs[t] = s; rq[t] = q;
    __syncthreads();
    for (int off = 128; off; off >>= 1) {
        if (t < off) { rs[t] += rs[t + off]; rq[t] += rq[t + off]; }
        __syncthreads();
    }
    if (t == 0) {
        const float mean = rs[0] * (1.0f / 32768.0f);
        const float var  = rq[0] * (1.0f / 32768.0f) - mean * mean;
        const float a    = g_alpha[ch & 255];
        const float inv  = gamma[ch] / sqrtf(a * a * var + 1e-5f);
        const float sc   = a * inv;                 // scale applied to S
        g_scale[ch] = sc;
        g_bias[ch]  = beta[ch] - mean * sc;
    }
}

// ---------------------------------------------------------------------------
// K3: threshold + merge + qrelu LUT; flag near-threshold pixels for k_fix.
// ---------------------------------------------------------------------------
__global__ void k_out(float* __restrict__ out) {
    const int idx = blockIdx.x * 256 + threadIdx.x;   // quad index
    const int b    = idx >> 16;
    const int qb   = idx & 65535;
    const int co   = qb >> 8;
    const int pix4 = qb & 255;

    const float4* pb = reinterpret_cast<const float4*>(g_psum);
    int c0 = 0, c1 = 0, c2 = 0, c3 = 0;
    bool f0 = false, f1 = false, f2 = false, f3 = false;
#pragma unroll
    for (int g = 0; g < 4; g++) {
        const int chan = g * 256 + co;
        const float4 p = pb[(size_t)(b * 1024 + chan) * 256 + pix4];
        const float sc = g_scale[chan];
        const float bi = g_bias[chan];
        const float band = fabsf(sc) * TAU;
        const float m0 = p.x * sc + bi;
        const float m1 = p.y * sc + bi;
        const float m2 = p.z * sc + bi;
        const float m3 = p.w * sc + bi;
        c0 += (m0 >= 0.0f); f0 |= (fabsf(m0) < band);
        c1 += (m1 >= 0.0f); f1 |= (fabsf(m1) < band);
        c2 += (m2 >= 0.0f); f2 |= (fabsf(m2) < band);
        c3 += (m3 >= 0.0f); f3 |= (fabsf(m3) < band);
    }
    const float Q3 = (8.0f / 15.0f) * 4.0f;
    float4 o;
    o.x = (c0 == 4) ? 4.0f : ((c0 == 3) ? Q3 : 0.0f);
    o.y = (c1 == 4) ? 4.0f : ((c1 == 3) ? Q3 : 0.0f);
    o.z = (c2 == 4) ? 4.0f : ((c2 == 3) ? Q3 : 0.0f);
    o.w = (c3 == 4) ? 4.0f : ((c3 == 3) ? Q3 : 0.0f);
    reinterpret_cast<float4*>(out)[idx] = o;

    if (f0 | f1 | f2 | f3) {
        const int base = (b << 18) | (co << 10) | (pix4 << 2);
#pragma unroll
        for (int comp = 0; comp < 4; ++comp) {
            const bool f = (comp == 0) ? f0 : (comp == 1) ? f1 : (comp == 2) ? f2 : f3;
            if (f) {
                const int slot = atomicAdd(&g_cnt, 1);
                if (slot < CAP) g_list[slot] = base | comp;
            }
        }
    }
}

// ---------------------------------------------------------------------------
// K4: exact (double) recompute of flagged pixels' decisions; rewrite out.
// Idempotent: result independent of list order / duplicates.
// ---------------------------------------------------------------------------
__global__ void k_fix(const float* __restrict__ x, const float* __restrict__ w,
                      float* __restrict__ out) {
    const int n = (g_cnt < CAP) ? g_cnt : CAP;
    for (int i = blockIdx.x * blockDim.x + threadIdx.x; i < n;
         i += gridDim.x * blockDim.x) {
        const int item = g_list[i];
        const int b   = item >> 18;
        const int co  = (item >> 10) & 255;
        const int pix = item & 1023;
        const int h = pix >> 5, wp = pix & 31;
        int c = 0;
#pragma unroll 1
        for (int g = 0; g < 4; g++) {
            const int chan = g * 256 + co;
            const float sc = g_scale[chan];
            const float bi = g_bias[chan];
            const float S  = g_psum[((size_t)(b * 1024 + chan)) * 1024 + pix];
            const float m  = S * sc + bi;
            int bit;
            if (fabsf(m) < fabsf(sc) * TAU) {
                double s = 0.0;
                const float* xb = x + ((size_t)(b * 256 + g * 64)) * 1024;
                const float* wb = w + (size_t)co * 2304 + (size_t)g * 64 * 9;
                for (int cig = 0; cig < 64; cig++) {
                    const float* xc = xb + cig * 1024;
                    const float* wc = wb + cig * 9;
#pragma unroll
                    for (int kh = 0; kh < 3; kh++) {
                        const int hh = h + kh - 1;
                        if ((unsigned)hh >= 32u) continue;
#pragma unroll
                        for (int kw = 0; kw < 3; kw++) {
                            const int ww = wp + kw - 1;
                            if ((unsigned)ww >= 32u) continue;
                            const float xv = __ldg(xc + hh * 32 + ww);
                            s += (__ldg(wc + kh * 3 + kw) >= 0.0f) ? (double)xv
                                                                   : -(double)xv;
                        }
                    }
                }
                const double md = s * (double)sc + (double)bi;
                bit = (md >= 0.0);
            } else {
                bit = (m >= 0.0f);
            }
            c += bit;
        }
        const float Q3 = (8.0f / 15.0f) * 4.0f;
        out[((size_t)(b * 256 + co)) * 1024 + pix] =
            (c == 4) ? 4.0f : ((c == 3) ? Q3 : 0.0f);
    }
}

// ---------------------------------------------------------------------------
extern "C" void kernel_launch(void* const* d_in, const int* in_sizes, int n_in,
                              void* d_out, int out_size) {
    const float* x      = (const float*)d_in[0];
    const float* weight = (const float*)d_in[1];
    const float* gamma  = (const float*)d_in[2];
    const float* beta   = (const float*)d_in[3];
    float* out = (float*)d_out;

    cudaFuncSetAttribute(k_conv, cudaFuncAttributeMaxDynamicSharedMemorySize, SM_BYTES);

    k_prep<<<256, 256>>>(weight);
    k_conv<<<dim3(8, 4, 32), 512, SM_BYTES>>>(x);
    k_stats<<<1024, 256>>>(gamma, beta);
    k_out<<<8192, 256>>>(out);
    k_fix<<<512, 128>>>(x, weight, out);
}